// round 7
// baseline (speedup 1.0000x reference)
#include <cuda_runtime.h>
#include <cuda_bf16.h>
#include <math.h>
#include <stdint.h>

#define BDIM 2048
#define HDIM 1024
#define BH (BDIM * HDIM)
#define HH ((size_t)HDIM * HDIM)

// ---------------- fp32 scratch pool ----------------------------------------
enum {
    P_XSL  = 0,   // 3
    P_HSR0 = 3,
    P_HSR1 = 4,
    P_Z1   = 5,
    P_R    = 6,
    P_HSL  = 7,   // 3
    P_RR   = 10,  // 3
    P_Z1R  = 13,  // 3
    P_RH   = 16,
    P_OMZ  = 17,
    P_Z2H  = 18,
    P_RHR  = 19,  // 3
    P_OMZR = 22,  // 3
    P_HT   = 25,
    P_HTL  = 26,  // 3
    P_ZH   = 29,
    P_ZHL  = 30,  // 3
    P_Z2HR = 33,  // 3
    P_TOTAL = 36
};
__device__ float g_pool[(size_t)P_TOTAL * BH];

// bf16 hi/lo activation slots (each BH elements)
enum {
    A_XH = 0, A_XL, A_HPH, A_HPL, A_Z1H, A_Z1L, A_RHI, A_RLO,
    A_RHH, A_RHL, A_OMZH, A_OMZL, A_HTH, A_HTL, A_ZHH, A_ZHL,
    A_Z2HH, A_Z2HL, A_TOTAL
};
__device__ __nv_bfloat16 g_act[(size_t)A_TOTAL * BH];

// transposed+split weights: mat m in 0..5 (L0..2, R0..2), hi/lo, layout [N=1024][K=1024]
__device__ __nv_bfloat16 g_wt[(size_t)12 * HH];

// ======================= PTX helpers ========================================
__device__ __forceinline__ uint32_t smem_u32(const void* p) {
    uint32_t a;
    asm("{ .reg .u64 t; cvta.to.shared.u64 t, %1; cvt.u32.u64 %0, t; }"
        : "=r"(a) : "l"(p));
    return a;
}

__device__ __forceinline__ void cpasync16(uint32_t smem, const void* g) {
    asm volatile("cp.async.cg.shared.global [%0], [%1], 16;" :: "r"(smem), "l"(g));
}
#define CP_COMMIT() asm volatile("cp.async.commit_group;" ::: "memory")
#define CP_WAIT1()  asm volatile("cp.async.wait_group 1;" ::: "memory")
#define CP_WAIT0()  asm volatile("cp.async.wait_group 0;" ::: "memory")

__device__ __forceinline__ void ldm_x4(uint32_t* r, uint32_t addr) {
    asm volatile("ldmatrix.sync.aligned.m8n8.x4.shared.b16 {%0,%1,%2,%3}, [%4];"
                 : "=r"(r[0]), "=r"(r[1]), "=r"(r[2]), "=r"(r[3]) : "r"(addr));
}

__device__ __forceinline__ void mma_bf16(float* c, const uint32_t* a,
                                         uint32_t b0, uint32_t b1) {
    asm volatile(
        "mma.sync.aligned.m16n8k16.row.col.f32.bf16.bf16.f32 "
        "{%0,%1,%2,%3}, {%4,%5,%6,%7}, {%8,%9}, {%0,%1,%2,%3};"
        : "+f"(c[0]), "+f"(c[1]), "+f"(c[2]), "+f"(c[3])
        : "r"(a[0]), "r"(a[1]), "r"(a[2]), "r"(a[3]), "r"(b0), "r"(b1));
}

// ======================= mma.sync batched GEMM ===============================
// C(2048x1024,f32) = A(2048x1024) @ Wt^T, A/Wt as bf16 hi/lo pairs,
// Wt stored [N=1024][K=1024] K-major. CTA tile 128x128, kc=32, 3-stage cp.async.
struct Job {
    const __nv_bfloat16* Ah; const __nv_bfloat16* Al;
    const __nv_bfloat16* Bh; const __nv_bfloat16* Bl;
    float* C;
};
struct JobBatch { Job j[9]; };

#define BK      32
#define KITERS  (HDIM / BK)   // 32
#define ROWSTR  80u           // bytes per smem row (40 bf16): conflict-free ldmatrix
#define REGION  10240u        // 128 rows * 80 B
#define STAGEB  40960u        // Ah + Al + Bh + Bl
#define NSTAGE  3
#define GSMEM   (NSTAGE * STAGEB)

__global__ void __launch_bounds__(256, 1) gemm_mma(JobBatch batch) {
    extern __shared__ char dsm[];
    const Job job = batch.j[blockIdx.z];
    const int tid  = threadIdx.x;
    const int lane = tid & 31;
    const int wid  = tid >> 5;
    const int m0 = blockIdx.y * 128, n0 = blockIdx.x * 128;
    const int wm = (wid & 1) * 64;     // warp M offset in tile
    const int wn = (wid >> 1) * 32;    // warp N offset in tile

    const uint32_t sb = smem_u32(dsm);

    const __nv_bfloat16* gp[4] = {job.Ah, job.Al, job.Bh, job.Bl};
    const int row0[4] = {m0, m0, n0, n0};

    // per-thread gmem/smem load mapping: 512 16B-chunks per region, 2 per thread
    const int ldRow0 = tid >> 2, ldCh0 = tid & 3;           // idx = tid
    const int ldRow1 = (tid + 256) >> 2, ldCh1 = tid & 3;   // idx = tid+256

    auto load_stage = [&](int stage, int kt) {
        uint32_t base = sb + (uint32_t)stage * STAGEB;
#pragma unroll
        for (int rgn = 0; rgn < 4; rgn++) {
            uint32_t rb = base + (uint32_t)rgn * REGION;
            const __nv_bfloat16* g = gp[rgn] + (size_t)row0[rgn] * HDIM + kt;
            cpasync16(rb + (uint32_t)ldRow0 * ROWSTR + (uint32_t)ldCh0 * 16u,
                      g + (size_t)ldRow0 * HDIM + ldCh0 * 8);
            cpasync16(rb + (uint32_t)ldRow1 * ROWSTR + (uint32_t)ldCh1 * 16u,
                      g + (size_t)ldRow1 * HDIM + ldCh1 * 8);
        }
    };

    float acc[4][4][4];
#pragma unroll
    for (int i = 0; i < 4; i++)
#pragma unroll
        for (int j = 0; j < 4; j++)
#pragma unroll
            for (int q = 0; q < 4; q++) acc[i][j][q] = 0.f;

    // ldmatrix lane-derived offsets
    const uint32_t aRow = (uint32_t)(wm + (lane & 15));
    const uint32_t aC8  = (uint32_t)((lane >> 4) * 8);         // elems
    const uint32_t bRow = (uint32_t)(wn + ((lane >> 4) & 1) * 8 + (lane & 7));
    const uint32_t bC8  = (uint32_t)(((lane >> 3) & 1) * 8);   // elems

    // prologue: stages 0 and 1 in flight (one commit group each)
    load_stage(0, 0);
    CP_COMMIT();
    load_stage(1, BK);
    CP_COMMIT();

    int buf = 0;
#pragma unroll 1
    for (int it = 0; it < KITERS; ++it) {
        // wait for stage `it`: while refills continue there are exactly 2 real
        // groups pending at this point (it, it+1) -> wait_group 1.
        // For the last two iterations no new groups are committed, so drain all.
        if (it < KITERS - 2) CP_WAIT1(); else CP_WAIT0();
        __syncthreads();
        // refill: buf (it+2)%3 == buf (it-1)%3, fully consumed by compute(it-1)
        // (every warp passed the syncthreads above after finishing it-1).
        if (it + 2 < KITERS) {
            int nb = buf + 2; if (nb >= NSTAGE) nb -= NSTAGE;
            load_stage(nb, (it + 2) * BK);
            CP_COMMIT();
        }

        const uint32_t base = sb + (uint32_t)buf * STAGEB;
#pragma unroll
        for (int ks = 0; ks < 2; ks++) {
            uint32_t ah[4][4], al[4][4], bh[2][4], bl[2][4];
#pragma unroll
            for (int mf = 0; mf < 4; mf++) {
                uint32_t ad = base + (aRow + (uint32_t)mf * 16u) * ROWSTR +
                              ((uint32_t)ks * 16u + aC8) * 2u;
                ldm_x4(ah[mf], ad);
                ldm_x4(al[mf], ad + REGION);
            }
#pragma unroll
            for (int p = 0; p < 2; p++) {
                uint32_t bd = base + 2u * REGION +
                              (bRow + (uint32_t)p * 16u) * ROWSTR +
                              ((uint32_t)ks * 16u + bC8) * 2u;
                ldm_x4(bh[p], bd);
                ldm_x4(bl[p], bd + REGION);
            }
            // split-outer ordering: each acc reused every 16 mma (no RAW stall)
#pragma unroll
            for (int mf = 0; mf < 4; mf++)
#pragma unroll
                for (int nf = 0; nf < 4; nf++)
                    mma_bf16(acc[mf][nf], ah[mf],
                             bh[nf >> 1][(nf & 1) * 2], bh[nf >> 1][(nf & 1) * 2 + 1]);
#pragma unroll
            for (int mf = 0; mf < 4; mf++)
#pragma unroll
                for (int nf = 0; nf < 4; nf++)
                    mma_bf16(acc[mf][nf], ah[mf],
                             bl[nf >> 1][(nf & 1) * 2], bl[nf >> 1][(nf & 1) * 2 + 1]);
#pragma unroll
            for (int mf = 0; mf < 4; mf++)
#pragma unroll
                for (int nf = 0; nf < 4; nf++)
                    mma_bf16(acc[mf][nf], al[mf],
                             bh[nf >> 1][(nf & 1) * 2], bh[nf >> 1][(nf & 1) * 2 + 1]);
        }
        buf++; if (buf >= NSTAGE) buf = 0;
    }

    // epilogue: direct f32 stores
    float* C = job.C + (size_t)m0 * HDIM + n0;
    const int r4 = lane >> 2, c2 = (lane & 3) * 2;
#pragma unroll
    for (int mf = 0; mf < 4; mf++)
#pragma unroll
        for (int nf = 0; nf < 4; nf++) {
            float* p0 = C + (size_t)(wm + mf * 16 + r4) * HDIM + wn + nf * 8 + c2;
            *(float2*)p0 = make_float2(acc[mf][nf][0], acc[mf][nf][1]);
            *(float2*)(p0 + 8 * HDIM) = make_float2(acc[mf][nf][2], acc[mf][nf][3]);
        }
}

// ---------------- weight transpose + bf16 split -----------------------------
__global__ void wsplit_kernel(const float* __restrict__ L, const float* __restrict__ R,
                              __nv_bfloat16* __restrict__ wt) {
    __shared__ float s[32][33];
    const int m = blockIdx.z;  // 0..5
    const float* W = (m < 3) ? (L + (size_t)m * HH) : (R + (size_t)(m - 3) * HH);
    __nv_bfloat16* dh = wt + (size_t)(2 * m) * HH;
    __nv_bfloat16* dl = wt + (size_t)(2 * m + 1) * HH;
    const int k0 = blockIdx.y * 32, n0 = blockIdx.x * 32;
    const int tx = threadIdx.x, ty = threadIdx.y;
#pragma unroll
    for (int j = 0; j < 32; j += 8)
        s[ty + j][tx] = W[(size_t)(k0 + ty + j) * HDIM + n0 + tx];
    __syncthreads();
#pragma unroll
    for (int j = 0; j < 32; j += 8) {
        float v = s[tx][ty + j];
        __nv_bfloat16 h = __float2bfloat16(v);
        size_t o = (size_t)(n0 + ty + j) * HDIM + k0 + tx;
        dh[o] = h;
        dl[o] = __float2bfloat16(v - __bfloat162float(h));
    }
}

// ---------------- activation bf16 split -------------------------------------
__global__ void asplit_kernel(const float* __restrict__ a,
                              __nv_bfloat16* __restrict__ hi,
                              __nv_bfloat16* __restrict__ lo) {
    int i = blockIdx.x * 256 + threadIdx.x;
    if (i >= BH) return;
    float v = a[i];
    __nv_bfloat16 h = __float2bfloat16(v);
    hi[i] = h;
    lo[i] = __float2bfloat16(v - __bfloat162float(h));
}

// ---------------- fused double sigmoid (+ splits) ---------------------------
__global__ void sig_kernel(const float* __restrict__ xsL0, const float* __restrict__ hsR0,
                           const float* __restrict__ xsL1, const float* __restrict__ hsR1,
                           const float* __restrict__ bias,
                           float* __restrict__ z1, float* __restrict__ r,
                           __nv_bfloat16* __restrict__ z1h, __nv_bfloat16* __restrict__ z1l,
                           __nv_bfloat16* __restrict__ rh, __nv_bfloat16* __restrict__ rl) {
    int i = blockIdx.x * blockDim.x + threadIdx.x;
    if (i >= BH) return;
    int h = i & (HDIM - 1);
    float t0 = xsL0[i] + hsR0[i] + bias[h];
    float t1 = xsL1[i] + hsR1[i] + bias[HDIM + h];
    float v0 = 1.f / (1.f + expf(-t0));
    float v1 = 1.f / (1.f + expf(-t1));
    z1[i] = v0; r[i] = v1;
    __nv_bfloat16 h0 = __float2bfloat16(v0);
    __nv_bfloat16 h1 = __float2bfloat16(v1);
    z1h[i] = h0; z1l[i] = __float2bfloat16(v0 - __bfloat162float(h0));
    rh[i]  = h1; rl[i]  = __float2bfloat16(v1 - __bfloat162float(h1));
}

// ---------------- mix kernel (+ optional bf16 split output) -----------------
enum { MIX_MUL = 0, MIX_ADD = 1, MIX_ONEMINUS = 2, MIX_TANH = 3 };

template <int OP>
__global__ void __launch_bounds__(256) mix_kernel(
    const float* __restrict__ A3, const float* __restrict__ B3,
    const float* __restrict__ a3, const float* __restrict__ b3,
    const float* __restrict__ bias, const float* __restrict__ w,
    float* __restrict__ out,
    __nv_bfloat16* __restrict__ oh, __nv_bfloat16* __restrict__ ol,
    float* gout, int gcol) {
    const int brow = blockIdx.x;
    const int tid  = threadIdx.x;
    __shared__ float cs[4 * HDIM];
    __shared__ float red[4][8];
    __shared__ float probs[4];

    float part[4] = {0.f, 0.f, 0.f, 0.f};
#pragma unroll
    for (int k = 0; k < 4; k++) {
        const float* pa = (k < 3) ? A3 + (size_t)k * BH + (size_t)brow * HDIM
                                  : a3 + (size_t)brow * HDIM;
        const float* pb = nullptr;
        if (OP != MIX_ONEMINUS)
            pb = (k < 3) ? B3 + (size_t)k * BH + (size_t)brow * HDIM
                         : b3 + (size_t)brow * HDIM;
        for (int h = tid; h < HDIM; h += 256) {
            float bb = bias[k * HDIM + h];
            float c;
            if (OP == MIX_MUL)           c = pa[h] * pb[h] + bb;
            else if (OP == MIX_ADD)      c = pa[h] + pb[h] + bb;
            else if (OP == MIX_ONEMINUS) c = 1.f - (pa[h] + bb);
            else                         c = tanhf(pa[h] + pb[h] + bb);
            cs[k * HDIM + h] = c;
            part[k] += c * w[h];
        }
    }
#pragma unroll
    for (int k = 0; k < 4; k++) {
        float v = part[k];
#pragma unroll
        for (int off = 16; off > 0; off >>= 1)
            v += __shfl_xor_sync(0xffffffffu, v, off);
        if ((tid & 31) == 0) red[k][tid >> 5] = v;
    }
    __syncthreads();
    if (tid == 0) {
        float s[4];
#pragma unroll
        for (int k = 0; k < 4; k++) {
            float t = 0.f;
#pragma unroll
            for (int wq = 0; wq < 8; wq++) t += red[k][wq];
            s[k] = t;
        }
        int g = 0; float mx = s[0];
#pragma unroll
        for (int k = 1; k < 4; k++) if (s[k] > mx) { mx = s[k]; g = k; }
        float e[4], den = 0.f;
#pragma unroll
        for (int k = 0; k < 4; k++) { e[k] = expf(s[k] - mx); den += e[k]; }
#pragma unroll
        for (int k = 0; k < 4; k++) probs[k] = e[k] / den;
        if (gout) gout[(size_t)brow * 9 + gcol] = (float)g;
    }
    __syncthreads();
    float p0 = probs[0], p1 = probs[1], p2 = probs[2], p3 = probs[3];
    for (int h = tid; h < HDIM; h += 256) {
        float v = p0 * cs[h] + p1 * cs[HDIM + h] + p2 * cs[2 * HDIM + h] +
                  p3 * cs[3 * HDIM + h];
        size_t idx = (size_t)brow * HDIM + h;
        out[idx] = v;
        if (oh) {
            __nv_bfloat16 hh = __float2bfloat16(v);
            oh[idx] = hh;
            ol[idx] = __float2bfloat16(v - __bfloat162float(hh));
        }
    }
}

__global__ void gzero_kernel(float* G) {
    int i = blockIdx.x * blockDim.x + threadIdx.x;
    if (i < BDIM * 3) G[(size_t)(i / 3) * 9 + (i % 3)] = 0.f;
}

// ---------------- orchestration ---------------------------------------------
extern "C" void kernel_launch(void* const* d_in, const int* in_sizes, int n_in,
                              void* d_out, int out_size) {
    const float* x    = (const float*)d_in[0];
    const float* hp   = (const float*)d_in[1];
    const float* L    = (const float*)d_in[2];
    const float* R    = (const float*)d_in[3];
    const float* bias = (const float*)d_in[4];
    const float* w    = (const float*)d_in[5];
    float* out = (float*)d_out;

    float* pool = nullptr;
    __nv_bfloat16* act = nullptr;
    __nv_bfloat16* wt  = nullptr;
    cudaGetSymbolAddress((void**)&pool, g_pool);
    cudaGetSymbolAddress((void**)&act,  g_act);
    cudaGetSymbolAddress((void**)&wt,   g_wt);
    auto P  = [&](int idx) { return pool + (size_t)idx * BH; };
    auto AB = [&](int idx) { return act + (size_t)idx * BH; };
    auto WT = [&](int m, int hl) { return wt + (size_t)(2 * m + hl) * HH; };
    // mats: 0..2 = L0..2, 3..5 = R0..2

    cudaFuncSetAttribute(gemm_mma, cudaFuncAttributeMaxDynamicSharedMemorySize, GSMEM);

    float* Gf = nullptr;
    if ((size_t)out_size >= (size_t)BH + (size_t)BDIM * 9) Gf = out + BH;

    // preprocessing: weight transpose+split, activation splits
    wsplit_kernel<<<dim3(32, 32, 6), dim3(32, 8)>>>(L, R, wt);
    asplit_kernel<<<BH / 256, 256>>>(x,  AB(A_XH),  AB(A_XL));
    asplit_kernel<<<BH / 256, 256>>>(hp, AB(A_HPH), AB(A_HPL));

    dim3 gg(8, 16, 1);

    // Stage 1: xs@L0..2, hs@R0, hs@R1
    {
        JobBatch bt;
        for (int k = 0; k < 3; k++)
            bt.j[k] = {AB(A_XH), AB(A_XL), WT(k, 0), WT(k, 1), P(P_XSL + k)};
        bt.j[3] = {AB(A_HPH), AB(A_HPL), WT(3, 0), WT(3, 1), P(P_HSR0)};
        bt.j[4] = {AB(A_HPH), AB(A_HPL), WT(4, 0), WT(4, 1), P(P_HSR1)};
        gg.z = 5;
        gemm_mma<<<gg, 256, GSMEM>>>(bt);
    }
    sig_kernel<<<BH / 256, 256>>>(P(P_XSL + 0), P(P_HSR0), P(P_XSL + 1), P(P_HSR1),
                                  bias, P(P_Z1), P(P_R),
                                  AB(A_Z1H), AB(A_Z1L), AB(A_RHI), AB(A_RLO));

    // Stage 2: hs@Lk, r@Rk, z1@Rk
    {
        JobBatch bt;
        for (int k = 0; k < 3; k++) {
            bt.j[k]     = {AB(A_HPH), AB(A_HPL), WT(k, 0),     WT(k, 1),     P(P_HSL + k)};
            bt.j[3 + k] = {AB(A_RHI), AB(A_RLO), WT(3 + k, 0), WT(3 + k, 1), P(P_RR + k)};
            bt.j[6 + k] = {AB(A_Z1H), AB(A_Z1L), WT(3 + k, 0), WT(3 + k, 1), P(P_Z1R + k)};
        }
        gg.z = 9;
        gemm_mma<<<gg, 256, GSMEM>>>(bt);
    }
    mix_kernel<MIX_MUL><<<BDIM, 256>>>(P(P_HSL), P(P_RR), hp, P(P_R), bias, w,
                                       P(P_RH), AB(A_RHH), AB(A_RHL), Gf, 3);
    mix_kernel<MIX_ONEMINUS><<<BDIM, 256>>>(P(P_Z1R), nullptr, P(P_Z1), nullptr, bias, w,
                                            P(P_OMZ), AB(A_OMZH), AB(A_OMZL), Gf, 5);
    mix_kernel<MIX_MUL><<<BDIM, 256>>>(P(P_HSL), P(P_Z1R), hp, P(P_Z1), bias, w,
                                       P(P_Z2H), AB(A_Z2HH), AB(A_Z2HL), Gf, 7);

    // Stage 3: rh@Rk, omz@Rk
    {
        JobBatch bt;
        for (int k = 0; k < 3; k++) {
            bt.j[k]     = {AB(A_RHH),  AB(A_RHL),  WT(3 + k, 0), WT(3 + k, 1), P(P_RHR + k)};
            bt.j[3 + k] = {AB(A_OMZH), AB(A_OMZL), WT(3 + k, 0), WT(3 + k, 1), P(P_OMZR + k)};
        }
        gg.z = 6;
        gemm_mma<<<gg, 256, GSMEM>>>(bt);
    }
    mix_kernel<MIX_TANH><<<BDIM, 256>>>(P(P_XSL), P(P_RHR), x, P(P_RH), bias, w,
                                        P(P_HT), AB(A_HTH), AB(A_HTL), Gf, 4);

    // Stage 4: ht@Lk
    {
        JobBatch bt;
        for (int k = 0; k < 3; k++)
            bt.j[k] = {AB(A_HTH), AB(A_HTL), WT(k, 0), WT(k, 1), P(P_HTL + k)};
        gg.z = 3;
        gemm_mma<<<gg, 256, GSMEM>>>(bt);
    }
    mix_kernel<MIX_MUL><<<BDIM, 256>>>(P(P_HTL), P(P_OMZR), P(P_HT), P(P_OMZ), bias, w,
                                       P(P_ZH), AB(A_ZHH), AB(A_ZHL), Gf, 6);

    // Stage 5: zh@Lk, z2h@Rk
    {
        JobBatch bt;
        for (int k = 0; k < 3; k++) {
            bt.j[k]     = {AB(A_ZHH),  AB(A_ZHL),  WT(k, 0),     WT(k, 1),     P(P_ZHL + k)};
            bt.j[3 + k] = {AB(A_Z2HH), AB(A_Z2HL), WT(3 + k, 0), WT(3 + k, 1), P(P_Z2HR + k)};
        }
        gg.z = 6;
        gemm_mma<<<gg, 256, GSMEM>>>(bt);
    }
    mix_kernel<MIX_ADD><<<BDIM, 256>>>(P(P_ZHL), P(P_Z2HR), P(P_ZH), P(P_Z2H), bias, w,
                                       out, nullptr, nullptr, Gf, 8);

    if (Gf) gzero_kernel<<<(BDIM * 3 + 255) / 256, 256>>>(Gf);
}

// round 8
// speedup vs baseline: 1.0841x; 1.0841x over previous
#include <cuda_runtime.h>
#include <cuda_bf16.h>
#include <math.h>
#include <stdint.h>

#define BDIM 2048
#define HDIM 1024
#define BH (BDIM * HDIM)
#define HH ((size_t)HDIM * HDIM)

// ---------------- fp32 scratch pool ----------------------------------------
enum {
    P_XSL  = 0,   // 3
    P_HSR0 = 3,
    P_HSR1 = 4,
    P_Z1   = 5,
    P_R    = 6,
    P_HSL  = 7,   // 3
    P_RR   = 10,  // 3
    P_Z1R  = 13,  // 3
    P_RH   = 16,
    P_OMZ  = 17,
    P_Z2H  = 18,
    P_RHR  = 19,  // 3
    P_OMZR = 22,  // 3
    P_HT   = 25,
    P_HTL  = 26,  // 3
    P_ZH   = 29,
    P_ZHL  = 30,  // 3
    P_Z2HR = 33,  // 3
    P_TOTAL = 36
};
__device__ float g_pool[(size_t)P_TOTAL * BH];

// bf16 hi/lo activation slots (each BH elements)
enum {
    A_XH = 0, A_XL, A_HPH, A_HPL, A_Z1H, A_Z1L, A_RHI, A_RLO,
    A_RHH, A_RHL, A_OMZH, A_OMZL, A_HTH, A_HTL, A_ZHH, A_ZHL,
    A_Z2HH, A_Z2HL, A_TOTAL
};
__device__ __nv_bfloat16 g_act[(size_t)A_TOTAL * BH];

// transposed+split weights: mat m in 0..5 (L0..2, R0..2), hi/lo, layout [N=1024][K=1024]
__device__ __nv_bfloat16 g_wt[(size_t)12 * HH];

// ======================= PTX helpers ========================================
__device__ __forceinline__ uint32_t smem_u32(const void* p) {
    uint32_t a;
    asm("{ .reg .u64 t; cvta.to.shared.u64 t, %1; cvt.u32.u64 %0, t; }"
        : "=r"(a) : "l"(p));
    return a;
}

__device__ __forceinline__ void cpasync16(uint32_t smem, const void* g) {
    asm volatile("cp.async.cg.shared.global [%0], [%1], 16;" :: "r"(smem), "l"(g));
}
#define CP_COMMIT() asm volatile("cp.async.commit_group;" ::: "memory")
#define CP_WAIT1()  asm volatile("cp.async.wait_group 1;" ::: "memory")
#define CP_WAIT0()  asm volatile("cp.async.wait_group 0;" ::: "memory")

__device__ __forceinline__ void ldm_x4(uint32_t* r, uint32_t addr) {
    asm volatile("ldmatrix.sync.aligned.m8n8.x4.shared.b16 {%0,%1,%2,%3}, [%4];"
                 : "=r"(r[0]), "=r"(r[1]), "=r"(r[2]), "=r"(r[3]) : "r"(addr));
}

__device__ __forceinline__ void mma_bf16(float* c, const uint32_t* a,
                                         uint32_t b0, uint32_t b1) {
    asm volatile(
        "mma.sync.aligned.m16n8k16.row.col.f32.bf16.bf16.f32 "
        "{%0,%1,%2,%3}, {%4,%5,%6,%7}, {%8,%9}, {%0,%1,%2,%3};"
        : "+f"(c[0]), "+f"(c[1]), "+f"(c[2]), "+f"(c[3])
        : "r"(a[0]), "r"(a[1]), "r"(a[2]), "r"(a[3]), "r"(b0), "r"(b1));
}

// ======================= mma.sync batched GEMM ===============================
// C(2048x1024,f32) = A(2048x1024) @ Wt^T, A/Wt as bf16 hi/lo pairs,
// Wt stored [N=1024][K=1024] K-major. CTA tile 128x128, kc=32,
// 2-stage cp.async, 2 CTAs/SM (occupancy is the binding constraint).
struct Job {
    const __nv_bfloat16* Ah; const __nv_bfloat16* Al;
    const __nv_bfloat16* Bh; const __nv_bfloat16* Bl;
    float* C;
};
struct JobBatch { Job j[9]; };

#define BK      32
#define KITERS  (HDIM / BK)   // 32
#define ROWSTR  80u           // bytes per smem row (40 bf16): conflict-free ldmatrix
#define REGION  10240u        // 128 rows * 80 B
#define STAGEB  40960u        // Ah + Al + Bh + Bl
#define NSTAGE  2
#define GSMEM   (NSTAGE * STAGEB)

__global__ void __launch_bounds__(256, 2) gemm_mma(JobBatch batch) {
    extern __shared__ char dsm[];
    const Job job = batch.j[blockIdx.z];
    const int tid  = threadIdx.x;
    const int lane = tid & 31;
    const int wid  = tid >> 5;
    const int m0 = blockIdx.y * 128, n0 = blockIdx.x * 128;
    const int wm = (wid & 1) * 64;     // warp M offset in tile
    const int wn = (wid >> 1) * 32;    // warp N offset in tile

    const uint32_t sb = smem_u32(dsm);

    const __nv_bfloat16* gp[4] = {job.Ah, job.Al, job.Bh, job.Bl};
    const int row0[4] = {m0, m0, n0, n0};

    // per-thread gmem/smem load mapping: 512 16B-chunks per region, 2 per thread
    const int ldRow0 = tid >> 2, ldCh0 = tid & 3;           // idx = tid
    const int ldRow1 = (tid + 256) >> 2, ldCh1 = tid & 3;   // idx = tid+256

    auto load_stage = [&](int stage, int kt) {
        uint32_t base = sb + (uint32_t)stage * STAGEB;
#pragma unroll
        for (int rgn = 0; rgn < 4; rgn++) {
            uint32_t rb = base + (uint32_t)rgn * REGION;
            const __nv_bfloat16* g = gp[rgn] + (size_t)row0[rgn] * HDIM + kt;
            cpasync16(rb + (uint32_t)ldRow0 * ROWSTR + (uint32_t)ldCh0 * 16u,
                      g + (size_t)ldRow0 * HDIM + ldCh0 * 8);
            cpasync16(rb + (uint32_t)ldRow1 * ROWSTR + (uint32_t)ldCh1 * 16u,
                      g + (size_t)ldRow1 * HDIM + ldCh1 * 8);
        }
    };

    float acc[4][4][4];
#pragma unroll
    for (int i = 0; i < 4; i++)
#pragma unroll
        for (int j = 0; j < 4; j++)
#pragma unroll
            for (int q = 0; q < 4; q++) acc[i][j][q] = 0.f;

    // ldmatrix lane-derived offsets
    const uint32_t aRow = (uint32_t)(wm + (lane & 15));
    const uint32_t aC8  = (uint32_t)((lane >> 4) * 8);         // elems
    const uint32_t bRow = (uint32_t)(wn + ((lane >> 4) & 1) * 8 + (lane & 7));
    const uint32_t bC8  = (uint32_t)(((lane >> 3) & 1) * 8);   // elems

    // prologue: both stages in flight
    load_stage(0, 0);
    CP_COMMIT();
    load_stage(1, BK);
    CP_COMMIT();

#pragma unroll 1
    for (int it = 0; it < KITERS; ++it) {
        const int buf = it & 1;
        if (it < KITERS - 1) CP_WAIT1(); else CP_WAIT0();
        __syncthreads();

        const uint32_t base = sb + (uint32_t)buf * STAGEB;
#pragma unroll
        for (int ks = 0; ks < 2; ks++) {
            // B fragments for this k16 (4 ldmatrix.x4)
            uint32_t bh[2][4], bl[2][4];
#pragma unroll
            for (int p = 0; p < 2; p++) {
                uint32_t bd = base + 2u * REGION +
                              (bRow + (uint32_t)p * 16u) * ROWSTR +
                              ((uint32_t)ks * 16u + bC8) * 2u;
                ldm_x4(bh[p], bd);
                ldm_x4(bl[p], bd + REGION);
            }
            // A fragments per mf, fire 12 MMAs immediately (low reg pressure)
#pragma unroll
            for (int mf = 0; mf < 4; mf++) {
                uint32_t ah[4], al[4];
                uint32_t ad = base + (aRow + (uint32_t)mf * 16u) * ROWSTR +
                              ((uint32_t)ks * 16u + aC8) * 2u;
                ldm_x4(ah, ad);
                ldm_x4(al, ad + REGION);
#pragma unroll
                for (int nf = 0; nf < 4; nf++) {
                    uint32_t h0 = bh[nf >> 1][(nf & 1) * 2];
                    uint32_t h1 = bh[nf >> 1][(nf & 1) * 2 + 1];
                    uint32_t l0 = bl[nf >> 1][(nf & 1) * 2];
                    uint32_t l1 = bl[nf >> 1][(nf & 1) * 2 + 1];
                    mma_bf16(acc[mf][nf], ah, h0, h1);
                    mma_bf16(acc[mf][nf], ah, l0, l1);
                    mma_bf16(acc[mf][nf], al, h0, h1);
                }
            }
        }
        __syncthreads();
        if (it + 2 < KITERS) {
            load_stage(buf, (it + 2) * BK);
            CP_COMMIT();
        }
    }

    // epilogue: direct f32 stores
    float* C = job.C + (size_t)m0 * HDIM + n0;
    const int r4 = lane >> 2, c2 = (lane & 3) * 2;
#pragma unroll
    for (int mf = 0; mf < 4; mf++)
#pragma unroll
        for (int nf = 0; nf < 4; nf++) {
            float* p0 = C + (size_t)(wm + mf * 16 + r4) * HDIM + wn + nf * 8 + c2;
            *(float2*)p0 = make_float2(acc[mf][nf][0], acc[mf][nf][1]);
            *(float2*)(p0 + 8 * HDIM) = make_float2(acc[mf][nf][2], acc[mf][nf][3]);
        }
}

// ---------------- weight transpose + bf16 split -----------------------------
__global__ void wsplit_kernel(const float* __restrict__ L, const float* __restrict__ R,
                              __nv_bfloat16* __restrict__ wt) {
    __shared__ float s[32][33];
    const int m = blockIdx.z;  // 0..5
    const float* W = (m < 3) ? (L + (size_t)m * HH) : (R + (size_t)(m - 3) * HH);
    __nv_bfloat16* dh = wt + (size_t)(2 * m) * HH;
    __nv_bfloat16* dl = wt + (size_t)(2 * m + 1) * HH;
    const int k0 = blockIdx.y * 32, n0 = blockIdx.x * 32;
    const int tx = threadIdx.x, ty = threadIdx.y;
#pragma unroll
    for (int j = 0; j < 32; j += 8)
        s[ty + j][tx] = W[(size_t)(k0 + ty + j) * HDIM + n0 + tx];
    __syncthreads();
#pragma unroll
    for (int j = 0; j < 32; j += 8) {
        float v = s[tx][ty + j];
        __nv_bfloat16 h = __float2bfloat16(v);
        size_t o = (size_t)(n0 + ty + j) * HDIM + k0 + tx;
        dh[o] = h;
        dl[o] = __float2bfloat16(v - __bfloat162float(h));
    }
}

// ---------------- activation bf16 split -------------------------------------
__global__ void asplit_kernel(const float* __restrict__ a,
                              __nv_bfloat16* __restrict__ hi,
                              __nv_bfloat16* __restrict__ lo) {
    int i = blockIdx.x * 256 + threadIdx.x;
    if (i >= BH) return;
    float v = a[i];
    __nv_bfloat16 h = __float2bfloat16(v);
    hi[i] = h;
    lo[i] = __float2bfloat16(v - __bfloat162float(h));
}

// ---------------- fused double sigmoid (+ splits) ---------------------------
__global__ void sig_kernel(const float* __restrict__ xsL0, const float* __restrict__ hsR0,
                           const float* __restrict__ xsL1, const float* __restrict__ hsR1,
                           const float* __restrict__ bias,
                           float* __restrict__ z1, float* __restrict__ r,
                           __nv_bfloat16* __restrict__ z1h, __nv_bfloat16* __restrict__ z1l,
                           __nv_bfloat16* __restrict__ rh, __nv_bfloat16* __restrict__ rl) {
    int i = blockIdx.x * blockDim.x + threadIdx.x;
    if (i >= BH) return;
    int h = i & (HDIM - 1);
    float t0 = xsL0[i] + hsR0[i] + bias[h];
    float t1 = xsL1[i] + hsR1[i] + bias[HDIM + h];
    float v0 = 1.f / (1.f + expf(-t0));
    float v1 = 1.f / (1.f + expf(-t1));
    z1[i] = v0; r[i] = v1;
    __nv_bfloat16 h0 = __float2bfloat16(v0);
    __nv_bfloat16 h1 = __float2bfloat16(v1);
    z1h[i] = h0; z1l[i] = __float2bfloat16(v0 - __bfloat162float(h0));
    rh[i]  = h1; rl[i]  = __float2bfloat16(v1 - __bfloat162float(h1));
}

// ---------------- mix kernel (+ optional bf16 split output) -----------------
enum { MIX_MUL = 0, MIX_ADD = 1, MIX_ONEMINUS = 2, MIX_TANH = 3 };

template <int OP>
__global__ void __launch_bounds__(256) mix_kernel(
    const float* __restrict__ A3, const float* __restrict__ B3,
    const float* __restrict__ a3, const float* __restrict__ b3,
    const float* __restrict__ bias, const float* __restrict__ w,
    float* __restrict__ out,
    __nv_bfloat16* __restrict__ oh, __nv_bfloat16* __restrict__ ol,
    float* gout, int gcol) {
    const int brow = blockIdx.x;
    const int tid  = threadIdx.x;
    __shared__ float cs[4 * HDIM];
    __shared__ float red[4][8];
    __shared__ float probs[4];

    float part[4] = {0.f, 0.f, 0.f, 0.f};
#pragma unroll
    for (int k = 0; k < 4; k++) {
        const float* pa = (k < 3) ? A3 + (size_t)k * BH + (size_t)brow * HDIM
                                  : a3 + (size_t)brow * HDIM;
        const float* pb = nullptr;
        if (OP != MIX_ONEMINUS)
            pb = (k < 3) ? B3 + (size_t)k * BH + (size_t)brow * HDIM
                         : b3 + (size_t)brow * HDIM;
        for (int h = tid; h < HDIM; h += 256) {
            float bb = bias[k * HDIM + h];
            float c;
            if (OP == MIX_MUL)           c = pa[h] * pb[h] + bb;
            else if (OP == MIX_ADD)      c = pa[h] + pb[h] + bb;
            else if (OP == MIX_ONEMINUS) c = 1.f - (pa[h] + bb);
            else                         c = tanhf(pa[h] + pb[h] + bb);
            cs[k * HDIM + h] = c;
            part[k] += c * w[h];
        }
    }
#pragma unroll
    for (int k = 0; k < 4; k++) {
        float v = part[k];
#pragma unroll
        for (int off = 16; off > 0; off >>= 1)
            v += __shfl_xor_sync(0xffffffffu, v, off);
        if ((tid & 31) == 0) red[k][tid >> 5] = v;
    }
    __syncthreads();
    if (tid == 0) {
        float s[4];
#pragma unroll
        for (int k = 0; k < 4; k++) {
            float t = 0.f;
#pragma unroll
            for (int wq = 0; wq < 8; wq++) t += red[k][wq];
            s[k] = t;
        }
        int g = 0; float mx = s[0];
#pragma unroll
        for (int k = 1; k < 4; k++) if (s[k] > mx) { mx = s[k]; g = k; }
        float e[4], den = 0.f;
#pragma unroll
        for (int k = 0; k < 4; k++) { e[k] = expf(s[k] - mx); den += e[k]; }
#pragma unroll
        for (int k = 0; k < 4; k++) probs[k] = e[k] / den;
        if (gout) gout[(size_t)brow * 9 + gcol] = (float)g;
    }
    __syncthreads();
    float p0 = probs[0], p1 = probs[1], p2 = probs[2], p3 = probs[3];
    for (int h = tid; h < HDIM; h += 256) {
        float v = p0 * cs[h] + p1 * cs[HDIM + h] + p2 * cs[2 * HDIM + h] +
                  p3 * cs[3 * HDIM + h];
        size_t idx = (size_t)brow * HDIM + h;
        out[idx] = v;
        if (oh) {
            __nv_bfloat16 hh = __float2bfloat16(v);
            oh[idx] = hh;
            ol[idx] = __float2bfloat16(v - __bfloat162float(hh));
        }
    }
}

__global__ void gzero_kernel(float* G) {
    int i = blockIdx.x * blockDim.x + threadIdx.x;
    if (i < BDIM * 3) G[(size_t)(i / 3) * 9 + (i % 3)] = 0.f;
}

// ---------------- orchestration ---------------------------------------------
extern "C" void kernel_launch(void* const* d_in, const int* in_sizes, int n_in,
                              void* d_out, int out_size) {
    const float* x    = (const float*)d_in[0];
    const float* hp   = (const float*)d_in[1];
    const float* L    = (const float*)d_in[2];
    const float* R    = (const float*)d_in[3];
    const float* bias = (const float*)d_in[4];
    const float* w    = (const float*)d_in[5];
    float* out = (float*)d_out;

    float* pool = nullptr;
    __nv_bfloat16* act = nullptr;
    __nv_bfloat16* wt  = nullptr;
    cudaGetSymbolAddress((void**)&pool, g_pool);
    cudaGetSymbolAddress((void**)&act,  g_act);
    cudaGetSymbolAddress((void**)&wt,   g_wt);
    auto P  = [&](int idx) { return pool + (size_t)idx * BH; };
    auto AB = [&](int idx) { return act + (size_t)idx * BH; };
    auto WT = [&](int m, int hl) { return wt + (size_t)(2 * m + hl) * HH; };
    // mats: 0..2 = L0..2, 3..5 = R0..2

    cudaFuncSetAttribute(gemm_mma, cudaFuncAttributeMaxDynamicSharedMemorySize, GSMEM);

    float* Gf = nullptr;
    if ((size_t)out_size >= (size_t)BH + (size_t)BDIM * 9) Gf = out + BH;

    // preprocessing: weight transpose+split, activation splits
    wsplit_kernel<<<dim3(32, 32, 6), dim3(32, 8)>>>(L, R, wt);
    asplit_kernel<<<BH / 256, 256>>>(x,  AB(A_XH),  AB(A_XL));
    asplit_kernel<<<BH / 256, 256>>>(hp, AB(A_HPH), AB(A_HPL));

    dim3 gg(8, 16, 1);

    // Stage 1: xs@L0..2, hs@R0, hs@R1
    {
        JobBatch bt;
        for (int k = 0; k < 3; k++)
            bt.j[k] = {AB(A_XH), AB(A_XL), WT(k, 0), WT(k, 1), P(P_XSL + k)};
        bt.j[3] = {AB(A_HPH), AB(A_HPL), WT(3, 0), WT(3, 1), P(P_HSR0)};
        bt.j[4] = {AB(A_HPH), AB(A_HPL), WT(4, 0), WT(4, 1), P(P_HSR1)};
        gg.z = 5;
        gemm_mma<<<gg, 256, GSMEM>>>(bt);
    }
    sig_kernel<<<BH / 256, 256>>>(P(P_XSL + 0), P(P_HSR0), P(P_XSL + 1), P(P_HSR1),
                                  bias, P(P_Z1), P(P_R),
                                  AB(A_Z1H), AB(A_Z1L), AB(A_RHI), AB(A_RLO));

    // Stage 2: hs@Lk, r@Rk, z1@Rk
    {
        JobBatch bt;
        for (int k = 0; k < 3; k++) {
            bt.j[k]     = {AB(A_HPH), AB(A_HPL), WT(k, 0),     WT(k, 1),     P(P_HSL + k)};
            bt.j[3 + k] = {AB(A_RHI), AB(A_RLO), WT(3 + k, 0), WT(3 + k, 1), P(P_RR + k)};
            bt.j[6 + k] = {AB(A_Z1H), AB(A_Z1L), WT(3 + k, 0), WT(3 + k, 1), P(P_Z1R + k)};
        }
        gg.z = 9;
        gemm_mma<<<gg, 256, GSMEM>>>(bt);
    }
    mix_kernel<MIX_MUL><<<BDIM, 256>>>(P(P_HSL), P(P_RR), hp, P(P_R), bias, w,
                                       P(P_RH), AB(A_RHH), AB(A_RHL), Gf, 3);
    mix_kernel<MIX_ONEMINUS><<<BDIM, 256>>>(P(P_Z1R), nullptr, P(P_Z1), nullptr, bias, w,
                                            P(P_OMZ), AB(A_OMZH), AB(A_OMZL), Gf, 5);
    mix_kernel<MIX_MUL><<<BDIM, 256>>>(P(P_HSL), P(P_Z1R), hp, P(P_Z1), bias, w,
                                       P(P_Z2H), AB(A_Z2HH), AB(A_Z2HL), Gf, 7);

    // Stage 3: rh@Rk, omz@Rk
    {
        JobBatch bt;
        for (int k = 0; k < 3; k++) {
            bt.j[k]     = {AB(A_RHH),  AB(A_RHL),  WT(3 + k, 0), WT(3 + k, 1), P(P_RHR + k)};
            bt.j[3 + k] = {AB(A_OMZH), AB(A_OMZL), WT(3 + k, 0), WT(3 + k, 1), P(P_OMZR + k)};
        }
        gg.z = 6;
        gemm_mma<<<gg, 256, GSMEM>>>(bt);
    }
    mix_kernel<MIX_TANH><<<BDIM, 256>>>(P(P_XSL), P(P_RHR), x, P(P_RH), bias, w,
                                        P(P_HT), AB(A_HTH), AB(A_HTL), Gf, 4);

    // Stage 4: ht@Lk
    {
        JobBatch bt;
        for (int k = 0; k < 3; k++)
            bt.j[k] = {AB(A_HTH), AB(A_HTL), WT(k, 0), WT(k, 1), P(P_HTL + k)};
        gg.z = 3;
        gemm_mma<<<gg, 256, GSMEM>>>(bt);
    }
    mix_kernel<MIX_MUL><<<BDIM, 256>>>(P(P_HTL), P(P_OMZR), P(P_HT), P(P_OMZ), bias, w,
                                       P(P_ZH), AB(A_ZHH), AB(A_ZHL), Gf, 6);

    // Stage 5: zh@Lk, z2h@Rk
    {
        JobBatch bt;
        for (int k = 0; k < 3; k++) {
            bt.j[k]     = {AB(A_ZHH),  AB(A_ZHL),  WT(k, 0),     WT(k, 1),     P(P_ZHL + k)};
            bt.j[3 + k] = {AB(A_Z2HH), AB(A_Z2HL), WT(3 + k, 0), WT(3 + k, 1), P(P_Z2HR + k)};
        }
        gg.z = 6;
        gemm_mma<<<gg, 256, GSMEM>>>(bt);
    }
    mix_kernel<MIX_ADD><<<BDIM, 256>>>(P(P_ZHL), P(P_Z2HR), P(P_ZH), P(P_Z2H), bias, w,
                                       out, nullptr, nullptr, Gf, 8);

    if (Gf) gzero_kernel<<<(BDIM * 3 + 255) / 256, 256>>>(Gf);
}

// round 10
// speedup vs baseline: 1.4176x; 1.3076x over previous
#include <cuda_runtime.h>
#include <cuda_fp16.h>
#include <math.h>
#include <stdint.h>

#define BDIM 2048
#define HDIM 1024
#define BH (BDIM * HDIM)
#define HH ((size_t)HDIM * HDIM)

// ---------------- fp32 scratch pool ----------------------------------------
enum {
    P_XSL  = 0,   // 3
    P_HSR0 = 3,
    P_HSR1 = 4,
    P_Z1   = 5,
    P_R    = 6,
    P_HSL  = 7,   // 3
    P_RR   = 10,  // 3
    P_Z1R  = 13,  // 3
    P_RH   = 16,
    P_OMZ  = 17,
    P_Z2H  = 18,
    P_RHR  = 19,  // 3
    P_OMZR = 22,  // 3
    P_HT   = 25,
    P_HTL  = 26,  // 3
    P_ZH   = 29,
    P_ZHL  = 30,  // 3
    P_Z2HR = 33,  // 3
    P_TOTAL = 36
};
__device__ float g_pool[(size_t)P_TOTAL * BH];

// fp16 hi/lo activation slots, K-chunk-tiled + pre-swizzled layout
enum {
    A_XH = 0, A_XL, A_HPH, A_HPL, A_Z1H, A_Z1L, A_RHI, A_RLO,
    A_RHH, A_RHL, A_OMZH, A_OMZL, A_HTH, A_HTL, A_ZHH, A_ZHL,
    A_Z2HH, A_Z2HL, A_TOTAL
};
__device__ __half g_act[(size_t)A_TOTAL * BH];

// transposed fp16 hi/lo weights, tiled layout: mat m 0..5 (L0..2,R0..2)
__device__ __half g_wt[(size_t)12 * HH];

// Tiled layout: element (row, h) -> kchunk = h/32 region of [ROWS][32],
// 64B rows, 16B chunks swizzled: chunk' = chunk ^ ((row>>1)&3).
__device__ __forceinline__ size_t toff(int row, int h, int rows) {
    return (size_t)(h >> 5) * ((size_t)rows * 32) + (size_t)row * 32 +
           (size_t)((((h >> 3) & 3) ^ ((row >> 1) & 3)) << 3) + (h & 7);
}

// ======================= PTX helpers ========================================
__device__ __forceinline__ uint32_t smem_u32(const void* p) {
    uint32_t a;
    asm("{ .reg .u64 t; cvta.to.shared.u64 t, %1; cvt.u32.u64 %0, t; }"
        : "=r"(a) : "l"(p));
    return a;
}

#define MBARRIER_INIT(mbar, count) \
    asm volatile("mbarrier.init.shared.b64 [%0], %1;" \
                 :: "r"((uint32_t)(mbar)), "r"((uint32_t)(count)) : "memory")

#define MBARRIER_EXPECT_TX(mbar, bytes) \
    asm volatile("mbarrier.arrive.expect_tx.shared.b64 _, [%0], %1;" \
                 :: "r"((uint32_t)(mbar)), "r"((uint32_t)(bytes)) : "memory")

#define MBARRIER_WAIT_PARITY(mbar, parity) do {                                   \
    uint32_t _m = (uint32_t)(mbar);                                               \
    uint32_t _p = (uint32_t)(parity);                                             \
    asm volatile(                                                                 \
        "{\n\t.reg .pred P1;\n\t"                                                 \
        "WAIT_LOOP_%=:\n\t"                                                       \
        "mbarrier.try_wait.parity.acquire.cta.shared::cta.b64 P1, [%0], %1, 0x989680;\n\t" \
        "@P1 bra.uni WAIT_DONE_%=;\n\t"                                           \
        "bra.uni WAIT_LOOP_%=;\n\t"                                               \
        "WAIT_DONE_%=:\n\t}"                                                      \
        :: "r"(_m), "r"(_p) : "memory");                                          \
} while (0)

__device__ __forceinline__ void bulk_g2s(uint32_t smem, const void* g,
                                         uint32_t bytes, uint32_t mbar) {
    asm volatile(
        "cp.async.bulk.shared::cluster.global.mbarrier::complete_tx::bytes "
        "[%0], [%1], %2, [%3];"
        :: "r"(smem), "l"(g), "r"(bytes), "r"(mbar) : "memory");
}

__device__ __forceinline__ void ldm_x4(uint32_t* r, uint32_t addr) {
    asm volatile("ldmatrix.sync.aligned.m8n8.x4.shared.b16 {%0,%1,%2,%3}, [%4];"
                 : "=r"(r[0]), "=r"(r[1]), "=r"(r[2]), "=r"(r[3]) : "r"(addr));
}

__device__ __forceinline__ void mma_f16(float* c, const uint32_t* a,
                                        uint32_t b0, uint32_t b1) {
    asm volatile(
        "mma.sync.aligned.m16n8k16.row.col.f32.f16.f16.f32 "
        "{%0,%1,%2,%3}, {%4,%5,%6,%7}, {%8,%9}, {%0,%1,%2,%3};"
        : "+f"(c[0]), "+f"(c[1]), "+f"(c[2]), "+f"(c[3])
        : "r"(a[0]), "r"(a[1]), "r"(a[2]), "r"(a[3]), "r"(b0), "r"(b1));
}

// ======================= bulk-copy batched GEMM ==============================
// C = (Ahi+Alo) @ (Bhi+Blo)^T, 3 passes (drop lo*lo), fp16 operands, f32 accum.
// Operands in tiled+swizzled layout. CTA tile 128x128, kc=32, 2 buffers,
// 2 CTAs/SM. 4 bulk copies per stage instead of 2048 LDGSTS.
struct Job {
    const __half* Ah; const __half* Al;
    const __half* Bh; const __half* Bl;
    float* C;
};
struct JobBatch { Job j[9]; };

#define KITERS  32
#define RGN     8192u          // 128 rows * 64B
#define STAGEB  32768u         // Ah + Al + Bh + Bl
#define GSMEM   (64 + 2 * 32768)

__global__ void __launch_bounds__(256, 2) gemm_mma(JobBatch batch) {
    extern __shared__ char dsm[];
    const Job job = batch.j[blockIdx.z];
    const int tid  = threadIdx.x;
    const int lane = tid & 31;
    const int wid  = tid >> 5;
    const int m0 = blockIdx.y * 128, n0 = blockIdx.x * 128;
    const int wm = (wid & 1) * 64;     // warp M offset
    const int wn = (wid >> 1) * 32;    // warp N offset

    const uint32_t sb  = smem_u32(dsm);
    const uint32_t stg = sb + 64;

    if (tid == 0) { MBARRIER_INIT(sb, 1); MBARRIER_INIT(sb + 8, 1); }
    __syncthreads();

    // A region source offset (halves): kc*2048*32 + m0*32 ; B: kc*1024*32 + n0*32
    auto issue = [&](int buf, int kc) {
        uint32_t s   = stg + (uint32_t)buf * STAGEB;
        uint32_t bar = sb + (uint32_t)buf * 8;
        MBARRIER_EXPECT_TX(bar, STAGEB);
        size_t ao = (size_t)kc * (2048 * 32) + (size_t)m0 * 32;
        size_t bo = (size_t)kc * (1024 * 32) + (size_t)n0 * 32;
        bulk_g2s(s,            job.Ah + ao, RGN, bar);
        bulk_g2s(s + RGN,      job.Al + ao, RGN, bar);
        bulk_g2s(s + 2 * RGN,  job.Bh + bo, RGN, bar);
        bulk_g2s(s + 3 * RGN,  job.Bl + bo, RGN, bar);
    };

    float acc[4][4][4];
#pragma unroll
    for (int i = 0; i < 4; i++)
#pragma unroll
        for (int j = 0; j < 4; j++)
#pragma unroll
            for (int q = 0; q < 4; q++) acc[i][j][q] = 0.f;

    if (tid == 0) { issue(0, 0); issue(1, 1); }

    int ph0 = 0, ph1 = 0;
#pragma unroll 1
    for (int it = 0; it < KITERS; ++it) {
        const int buf = it & 1;
        if (buf == 0) { MBARRIER_WAIT_PARITY(sb, ph0);     ph0 ^= 1; }
        else          { MBARRIER_WAIT_PARITY(sb + 8, ph1); ph1 ^= 1; }

        const uint32_t base = stg + (uint32_t)buf * STAGEB;
#pragma unroll
        for (int ks = 0; ks < 2; ks++) {
            // B fragments (hi & lo)
            uint32_t bh[2][4], bl[2][4];
#pragma unroll
            for (int p = 0; p < 2; p++) {
                int r = wn + p * 16 + ((lane >> 4) & 1) * 8 + (lane & 7);
                int c = ks * 2 + ((lane >> 3) & 1);
                uint32_t off = (uint32_t)r * 64u +
                               (uint32_t)((c ^ ((r >> 1) & 3)) << 4);
                ldm_x4(bh[p], base + 2u * RGN + off);
                ldm_x4(bl[p], base + 3u * RGN + off);
            }
            // mf-pair blocking: 16 frag regs live, reuse distance 8 MMAs
#pragma unroll
            for (int mfp = 0; mfp < 2; mfp++) {
                uint32_t ah[2][4], al[2][4];
#pragma unroll
                for (int q = 0; q < 2; q++) {
                    int mf = mfp * 2 + q;
                    int r = wm + mf * 16 + (lane & 15);
                    int c = ks * 2 + (lane >> 4);
                    uint32_t off = (uint32_t)r * 64u +
                                   (uint32_t)((c ^ ((r >> 1) & 3)) << 4);
                    ldm_x4(ah[q], base + off);
                    ldm_x4(al[q], base + RGN + off);
                }
#pragma unroll
                for (int q = 0; q < 2; q++)
#pragma unroll
                    for (int nf = 0; nf < 4; nf++)
                        mma_f16(acc[mfp * 2 + q][nf], ah[q],
                                bh[nf >> 1][(nf & 1) * 2], bh[nf >> 1][(nf & 1) * 2 + 1]);
#pragma unroll
                for (int q = 0; q < 2; q++)
#pragma unroll
                    for (int nf = 0; nf < 4; nf++)
                        mma_f16(acc[mfp * 2 + q][nf], al[q],
                                bh[nf >> 1][(nf & 1) * 2], bh[nf >> 1][(nf & 1) * 2 + 1]);
#pragma unroll
                for (int q = 0; q < 2; q++)
#pragma unroll
                    for (int nf = 0; nf < 4; nf++)
                        mma_f16(acc[mfp * 2 + q][nf], ah[q],
                                bl[nf >> 1][(nf & 1) * 2], bl[nf >> 1][(nf & 1) * 2 + 1]);
            }
        }
        __syncthreads();   // all warps done with buf before refill
        if (tid == 0 && it + 2 < KITERS) issue(buf, it + 2);
    }

    // epilogue: direct f32 stores
    float* C = job.C + (size_t)m0 * HDIM + n0;
    const int r4 = lane >> 2, c2 = (lane & 3) * 2;
#pragma unroll
    for (int mf = 0; mf < 4; mf++)
#pragma unroll
        for (int nf = 0; nf < 4; nf++) {
            float* p0 = C + (size_t)(wm + mf * 16 + r4) * HDIM + wn + nf * 8 + c2;
            *(float2*)p0 = make_float2(acc[mf][nf][0], acc[mf][nf][1]);
            *(float2*)(p0 + 8 * HDIM) = make_float2(acc[mf][nf][2], acc[mf][nf][3]);
        }
}

// ---------------- weight transpose + fp16 hi/lo (tiled layout) --------------
__global__ void wsplit_kernel(const float* __restrict__ L, const float* __restrict__ R,
                              __half* __restrict__ wt) {
    __shared__ float s[32][33];
    const int m = blockIdx.z;  // 0..5
    const float* W = (m < 3) ? (L + (size_t)m * HH) : (R + (size_t)(m - 3) * HH);
    __half* dh = wt + (size_t)(2 * m) * HH;
    __half* dl = wt + (size_t)(2 * m + 1) * HH;
    const int k0 = blockIdx.y * 32, n0 = blockIdx.x * 32;
    const int tx = threadIdx.x, ty = threadIdx.y;
#pragma unroll
    for (int j = 0; j < 32; j += 8)
        s[ty + j][tx] = W[(size_t)(k0 + ty + j) * HDIM + n0 + tx];
    __syncthreads();
#pragma unroll
    for (int j = 0; j < 32; j += 8) {
        float v = s[tx][ty + j];
        __half h = __float2half(v);
        size_t o = toff(n0 + ty + j, k0 + tx, 1024);
        dh[o] = h;
        dl[o] = __float2half(v - __half2float(h));
    }
}

// ---------------- activation fp16 split (tiled layout) ----------------------
__global__ void asplit_kernel(const float* __restrict__ a,
                              __half* __restrict__ hi,
                              __half* __restrict__ lo) {
    int i = blockIdx.x * 256 + threadIdx.x;
    if (i >= BH) return;
    float v = a[i];
    __half h = __float2half(v);
    size_t o = toff(i >> 10, i & 1023, 2048);
    hi[o] = h;
    lo[o] = __float2half(v - __half2float(h));
}

// ---------------- fused double sigmoid (+ tiled splits) ---------------------
__global__ void sig_kernel(const float* __restrict__ xsL0, const float* __restrict__ hsR0,
                           const float* __restrict__ xsL1, const float* __restrict__ hsR1,
                           const float* __restrict__ bias,
                           float* __restrict__ z1, float* __restrict__ r,
                           __half* __restrict__ z1h, __half* __restrict__ z1l,
                           __half* __restrict__ rh, __half* __restrict__ rl) {
    int i = blockIdx.x * blockDim.x + threadIdx.x;
    if (i >= BH) return;
    int h = i & (HDIM - 1);
    float t0 = xsL0[i] + hsR0[i] + bias[h];
    float t1 = xsL1[i] + hsR1[i] + bias[HDIM + h];
    float v0 = 1.f / (1.f + expf(-t0));
    float v1 = 1.f / (1.f + expf(-t1));
    z1[i] = v0; r[i] = v1;
    size_t o = toff(i >> 10, h, 2048);
    __half h0 = __float2half(v0);
    __half h1 = __float2half(v1);
    z1h[o] = h0; z1l[o] = __float2half(v0 - __half2float(h0));
    rh[o]  = h1; rl[o]  = __float2half(v1 - __half2float(h1));
}

// ---------------- mix kernel (+ optional tiled fp16 split output) -----------
enum { MIX_MUL = 0, MIX_ADD = 1, MIX_ONEMINUS = 2, MIX_TANH = 3 };

template <int OP>
__global__ void __launch_bounds__(256) mix_kernel(
    const float* __restrict__ A3, const float* __restrict__ B3,
    const float* __restrict__ a3, const float* __restrict__ b3,
    const float* __restrict__ bias, const float* __restrict__ w,
    float* __restrict__ out,
    __half* __restrict__ oh, __half* __restrict__ ol,
    float* gout, int gcol) {
    const int brow = blockIdx.x;
    const int tid  = threadIdx.x;
    __shared__ float cs[4 * HDIM];
    __shared__ float red[4][8];
    __shared__ float probs[4];

    float part[4] = {0.f, 0.f, 0.f, 0.f};
#pragma unroll
    for (int k = 0; k < 4; k++) {
        const float* pa = (k < 3) ? A3 + (size_t)k * BH + (size_t)brow * HDIM
                                  : a3 + (size_t)brow * HDIM;
        const float* pb = nullptr;
        if (OP != MIX_ONEMINUS)
            pb = (k < 3) ? B3 + (size_t)k * BH + (size_t)brow * HDIM
                         : b3 + (size_t)brow * HDIM;
        for (int h = tid; h < HDIM; h += 256) {
            float bb = bias[k * HDIM + h];
            float c;
            if (OP == MIX_MUL)           c = pa[h] * pb[h] + bb;
            else if (OP == MIX_ADD)      c = pa[h] + pb[h] + bb;
            else if (OP == MIX_ONEMINUS) c = 1.f - (pa[h] + bb);
            else                         c = tanhf(pa[h] + pb[h] + bb);
            cs[k * HDIM + h] = c;
            part[k] += c * w[h];
        }
    }
#pragma unroll
    for (int k = 0; k < 4; k++) {
        float v = part[k];
#pragma unroll
        for (int off = 16; off > 0; off >>= 1)
            v += __shfl_xor_sync(0xffffffffu, v, off);
        if ((tid & 31) == 0) red[k][tid >> 5] = v;
    }
    __syncthreads();
    if (tid == 0) {
        float s[4];
#pragma unroll
        for (int k = 0; k < 4; k++) {
            float t = 0.f;
#pragma unroll
            for (int wq = 0; wq < 8; wq++) t += red[k][wq];
            s[k] = t;
        }
        int g = 0; float mx = s[0];
#pragma unroll
        for (int k = 1; k < 4; k++) if (s[k] > mx) { mx = s[k]; g = k; }
        float e[4], den = 0.f;
#pragma unroll
        for (int k = 0; k < 4; k++) { e[k] = expf(s[k] - mx); den += e[k]; }
#pragma unroll
        for (int k = 0; k < 4; k++) probs[k] = e[k] / den;
        if (gout) gout[(size_t)brow * 9 + gcol] = (float)g;
    }
    __syncthreads();
    float p0 = probs[0], p1 = probs[1], p2 = probs[2], p3 = probs[3];
    for (int h = tid; h < HDIM; h += 256) {
        float v = p0 * cs[h] + p1 * cs[HDIM + h] + p2 * cs[2 * HDIM + h] +
                  p3 * cs[3 * HDIM + h];
        out[(size_t)brow * HDIM + h] = v;
        if (oh) {
            size_t o = toff(brow, h, 2048);
            __half hh = __float2half(v);
            oh[o] = hh;
            ol[o] = __float2half(v - __half2float(hh));
        }
    }
}

__global__ void gzero_kernel(float* G) {
    int i = blockIdx.x * blockDim.x + threadIdx.x;
    if (i < BDIM * 3) G[(size_t)(i / 3) * 9 + (i % 3)] = 0.f;
}

// ---------------- orchestration ---------------------------------------------
extern "C" void kernel_launch(void* const* d_in, const int* in_sizes, int n_in,
                              void* d_out, int out_size) {
    const float* x    = (const float*)d_in[0];
    const float* hp   = (const float*)d_in[1];
    const float* L    = (const float*)d_in[2];
    const float* R    = (const float*)d_in[3];
    const float* bias = (const float*)d_in[4];
    const float* w    = (const float*)d_in[5];
    float* out = (float*)d_out;

    float* pool = nullptr;
    __half* act = nullptr;
    __half* wt  = nullptr;
    cudaGetSymbolAddress((void**)&pool, g_pool);
    cudaGetSymbolAddress((void**)&act,  g_act);
    cudaGetSymbolAddress((void**)&wt,   g_wt);
    auto P  = [&](int idx) { return pool + (size_t)idx * BH; };
    auto AB = [&](int idx) { return act + (size_t)idx * BH; };
    auto WT = [&](int m, int hl) { return wt + (size_t)(2 * m + hl) * HH; };
    // mats: 0..2 = L0..2, 3..5 = R0..2

    cudaFuncSetAttribute(gemm_mma, cudaFuncAttributeMaxDynamicSharedMemorySize, GSMEM);

    float* Gf = nullptr;
    if ((size_t)out_size >= (size_t)BH + (size_t)BDIM * 9) Gf = out + BH;

    // preprocessing
    wsplit_kernel<<<dim3(32, 32, 6), dim3(32, 8)>>>(L, R, wt);
    asplit_kernel<<<BH / 256, 256>>>(x,  AB(A_XH),  AB(A_XL));
    asplit_kernel<<<BH / 256, 256>>>(hp, AB(A_HPH), AB(A_HPL));

    dim3 gg(8, 16, 1);

    // Stage 1: xs@L0..2, hs@R0, hs@R1
    {
        JobBatch bt;
        for (int k = 0; k < 3; k++)
            bt.j[k] = {AB(A_XH), AB(A_XL), WT(k, 0), WT(k, 1), P(P_XSL + k)};
        bt.j[3] = {AB(A_HPH), AB(A_HPL), WT(3, 0), WT(3, 1), P(P_HSR0)};
        bt.j[4] = {AB(A_HPH), AB(A_HPL), WT(4, 0), WT(4, 1), P(P_HSR1)};
        gg.z = 5;
        gemm_mma<<<gg, 256, GSMEM>>>(bt);
    }
    sig_kernel<<<BH / 256, 256>>>(P(P_XSL + 0), P(P_HSR0), P(P_XSL + 1), P(P_HSR1),
                                  bias, P(P_Z1), P(P_R),
                                  AB(A_Z1H), AB(A_Z1L), AB(A_RHI), AB(A_RLO));

    // Stage 2: hs@Lk, r@Rk, z1@Rk
    {
        JobBatch bt;
        for (int k = 0; k < 3; k++) {
            bt.j[k]     = {AB(A_HPH), AB(A_HPL), WT(k, 0),     WT(k, 1),     P(P_HSL + k)};
            bt.j[3 + k] = {AB(A_RHI), AB(A_RLO), WT(3 + k, 0), WT(3 + k, 1), P(P_RR + k)};
            bt.j[6 + k] = {AB(A_Z1H), AB(A_Z1L), WT(3 + k, 0), WT(3 + k, 1), P(P_Z1R + k)};
        }
        gg.z = 9;
        gemm_mma<<<gg, 256, GSMEM>>>(bt);
    }
    mix_kernel<MIX_MUL><<<BDIM, 256>>>(P(P_HSL), P(P_RR), hp, P(P_R), bias, w,
                                       P(P_RH), AB(A_RHH), AB(A_RHL), Gf, 3);
    mix_kernel<MIX_ONEMINUS><<<BDIM, 256>>>(P(P_Z1R), nullptr, P(P_Z1), nullptr, bias, w,
                                            P(P_OMZ), AB(A_OMZH), AB(A_OMZL), Gf, 5);
    mix_kernel<MIX_MUL><<<BDIM, 256>>>(P(P_HSL), P(P_Z1R), hp, P(P_Z1), bias, w,
                                       P(P_Z2H), AB(A_Z2HH), AB(A_Z2HL), Gf, 7);

    // Stage 3: rh@Rk, omz@Rk
    {
        JobBatch bt;
        for (int k = 0; k < 3; k++) {
            bt.j[k]     = {AB(A_RHH),  AB(A_RHL),  WT(3 + k, 0), WT(3 + k, 1), P(P_RHR + k)};
            bt.j[3 + k] = {AB(A_OMZH), AB(A_OMZL), WT(3 + k, 0), WT(3 + k, 1), P(P_OMZR + k)};
        }
        gg.z = 6;
        gemm_mma<<<gg, 256, GSMEM>>>(bt);
    }
    mix_kernel<MIX_TANH><<<BDIM, 256>>>(P(P_XSL), P(P_RHR), x, P(P_RH), bias, w,
                                        P(P_HT), AB(A_HTH), AB(A_HTL), Gf, 4);

    // Stage 4: ht@Lk
    {
        JobBatch bt;
        for (int k = 0; k < 3; k++)
            bt.j[k] = {AB(A_HTH), AB(A_HTL), WT(k, 0), WT(k, 1), P(P_HTL + k)};
        gg.z = 3;
        gemm_mma<<<gg, 256, GSMEM>>>(bt);
    }
    mix_kernel<MIX_MUL><<<BDIM, 256>>>(P(P_HTL), P(P_OMZR), P(P_HT), P(P_OMZ), bias, w,
                                       P(P_ZH), AB(A_ZHH), AB(A_ZHL), Gf, 6);

    // Stage 5: zh@Lk, z2h@Rk
    {
        JobBatch bt;
        for (int k = 0; k < 3; k++) {
            bt.j[k]     = {AB(A_ZHH),  AB(A_ZHL),  WT(k, 0),     WT(k, 1),     P(P_ZHL + k)};
            bt.j[3 + k] = {AB(A_Z2HH), AB(A_Z2HL), WT(3 + k, 0), WT(3 + k, 1), P(P_Z2HR + k)};
        }
        gg.z = 6;
        gemm_mma<<<gg, 256, GSMEM>>>(bt);
    }
    mix_kernel<MIX_ADD><<<BDIM, 256>>>(P(P_ZHL), P(P_Z2HR), P(P_ZH), P(P_Z2H), bias, w,
                                       out, nullptr, nullptr, Gf, 8);

    if (Gf) gzero_kernel<<<(BDIM * 3 + 255) / 256, 256>>>(Gf);
}